// round 1
// baseline (speedup 1.0000x reference)
#include <cuda_runtime.h>
#include <math.h>

#define NB 4
#define NS 2048
#define ND 768
#define NH 12
#define HD 64
#define NTILES (NS/64)
#define LDA 68   // smem row stride (floats) for attention tiles

// Scratch (device globals — no allocation allowed)
__device__ float g_q[NB*NH*NS*HD];
__device__ float g_k[NB*NH*NS*HD];
__device__ float g_v[NB*NH*NS*HD];
__device__ float g_ctx[NB*NS*ND];

// ---------------------------------------------------------------------------
// 128x128x8 fp32 SGEMM, 256 threads, 8x8 per thread.
// mode 0: A = g_ctx, plain write to out_plain (+bias)      [output proj]
// mode 1/2/3: A = Ain, write split-heads to g_q/g_k/g_v    [QKV proj]
// ---------------------------------------------------------------------------
__global__ void __launch_bounds__(256) sgemm_kernel(
    const float* __restrict__ Ain, const float* __restrict__ W,
    const float* __restrict__ bias, float* __restrict__ out_plain, int mode)
{
    __shared__ float As[8][128];
    __shared__ float Bs[8][128];

    const float* A = (mode == 0) ? g_ctx : Ain;

    const int t  = threadIdx.x;
    const int m0 = blockIdx.y * 128;
    const int n0 = blockIdx.x * 128;
    const int tx = t & 15, ty = t >> 4;

    // global load mapping
    const int a_row = t >> 1,  a_k = (t & 1) * 4;   // A tile: 128 rows x 8 k
    const int b_row = t >> 5,  b_c = (t & 31) * 4;  // B tile: 8 rows x 128 n

    float acc[8][8];
    #pragma unroll
    for (int i = 0; i < 8; i++)
        #pragma unroll
        for (int j = 0; j < 8; j++) acc[i][j] = 0.f;

    for (int k0 = 0; k0 < ND; k0 += 8) {
        float4 av = *(const float4*)(A + (size_t)(m0 + a_row) * ND + k0 + a_k);
        float4 bv = *(const float4*)(W + (size_t)(k0 + b_row) * ND + n0 + b_c);
        __syncthreads();
        As[a_k + 0][a_row] = av.x;
        As[a_k + 1][a_row] = av.y;
        As[a_k + 2][a_row] = av.z;
        As[a_k + 3][a_row] = av.w;
        *(float4*)&Bs[b_row][b_c] = bv;
        __syncthreads();

        #pragma unroll
        for (int kk = 0; kk < 8; kk++) {
            float af[8], bf[8];
            *(float4*)(af)     = *(const float4*)&As[kk][ty * 8];
            *(float4*)(af + 4) = *(const float4*)&As[kk][ty * 8 + 4];
            // two contiguous float4 groups -> conflict-free smem reads
            *(float4*)(bf)     = *(const float4*)&Bs[kk][tx * 4];
            *(float4*)(bf + 4) = *(const float4*)&Bs[kk][64 + tx * 4];
            #pragma unroll
            for (int i = 0; i < 8; i++)
                #pragma unroll
                for (int j = 0; j < 8; j++)
                    acc[i][j] += af[i] * bf[j];
        }
    }

    if (mode == 0) {
        #pragma unroll
        for (int i = 0; i < 8; i++) {
            int m = m0 + ty * 8 + i;
            #pragma unroll
            for (int j = 0; j < 8; j++) {
                int n = n0 + ((j < 4) ? (tx * 4 + j) : (64 + tx * 4 + j - 4));
                out_plain[(size_t)m * ND + n] = acc[i][j] + bias[n];
            }
        }
    } else {
        float* out = (mode == 1) ? g_q : (mode == 2) ? g_k : g_v;
        #pragma unroll
        for (int i = 0; i < 8; i++) {
            int m  = m0 + ty * 8 + i;
            int bb = m / NS, s = m % NS;
            #pragma unroll
            for (int j = 0; j < 8; j++) {
                int n  = n0 + ((j < 4) ? (tx * 4 + j) : (64 + tx * 4 + j - 4));
                int h  = n >> 6, dd = n & 63;
                out[(((size_t)(bb * NH + h)) * NS + s) * HD + dd] = acc[i][j] + bias[n];
            }
        }
    }
}

// ---------------------------------------------------------------------------
// Flash attention fp32. One block = one (b, h, 64-row q-tile). 256 threads.
// Thread (tx,ty): score rows r0..r0+3 (ty*4), score cols / d-cols c0..c0+3 (tx*4).
// Half-warp shuffle reductions over tx for row max/sum.
// ---------------------------------------------------------------------------
__global__ void __launch_bounds__(256) attn_kernel()
{
    extern __shared__ float sm[];
    float* Qs = sm;
    float* Ks = sm + 64 * LDA;
    float* Vs = sm + 2 * 64 * LDA;
    float* Ps = sm + 3 * 64 * LDA;

    const int t  = threadIdx.x;
    const int qt = blockIdx.x, h = blockIdx.y, b = blockIdx.z;
    const float* qbase = g_q + ((size_t)(b * NH + h) * NS) * HD;
    const float* kbase = g_k + ((size_t)(b * NH + h) * NS) * HD;
    const float* vbase = g_v + ((size_t)(b * NH + h) * NS) * HD;

    const int tx = t & 15, ty = t >> 4;
    const int r0 = ty * 4, c0 = tx * 4;

    // load Q tile (64 x 64)
    #pragma unroll
    for (int i = 0; i < 4; i++) {
        int id = t + 256 * i;
        int row = id >> 4, c4 = (id & 15) << 2;
        *(float4*)&Qs[row * LDA + c4] =
            *(const float4*)&qbase[(size_t)(qt * 64 + row) * HD + c4];
    }

    float m_run[4], l_run[4], O[4][4];
    #pragma unroll
    for (int i = 0; i < 4; i++) {
        m_run[i] = -1e30f; l_run[i] = 0.f;
        #pragma unroll
        for (int j = 0; j < 4; j++) O[i][j] = 0.f;
    }
    __syncthreads();

    const float scale = 0.125f; // 1/sqrt(64)

    for (int jt = 0; jt < NTILES; jt++) {
        // load K, V tiles (64 x 64 each)
        #pragma unroll
        for (int i = 0; i < 4; i++) {
            int id = t + 256 * i;
            int row = id >> 4, c4 = (id & 15) << 2;
            *(float4*)&Ks[row * LDA + c4] =
                *(const float4*)&kbase[(size_t)(jt * 64 + row) * HD + c4];
            *(float4*)&Vs[row * LDA + c4] =
                *(const float4*)&vbase[(size_t)(jt * 64 + row) * HD + c4];
        }
        __syncthreads();

        // S = Q K^T (4x4 per thread)
        float sc[4][4];
        #pragma unroll
        for (int i = 0; i < 4; i++)
            #pragma unroll
            for (int j = 0; j < 4; j++) sc[i][j] = 0.f;

        #pragma unroll
        for (int d4 = 0; d4 < HD; d4 += 4) {
            float4 qf[4], kf[4];
            #pragma unroll
            for (int i = 0; i < 4; i++) qf[i] = *(const float4*)&Qs[(r0 + i) * LDA + d4];
            #pragma unroll
            for (int j = 0; j < 4; j++) kf[j] = *(const float4*)&Ks[(c0 + j) * LDA + d4];
            #pragma unroll
            for (int i = 0; i < 4; i++)
                #pragma unroll
                for (int j = 0; j < 4; j++)
                    sc[i][j] += qf[i].x * kf[j].x + qf[i].y * kf[j].y
                              + qf[i].z * kf[j].z + qf[i].w * kf[j].w;
        }

        // online softmax (per row, reduced across the 16 tx lanes)
        #pragma unroll
        for (int i = 0; i < 4; i++) {
            float tmax = -1e30f;
            #pragma unroll
            for (int j = 0; j < 4; j++) {
                sc[i][j] *= scale;
                tmax = fmaxf(tmax, sc[i][j]);
            }
            #pragma unroll
            for (int off = 8; off; off >>= 1)
                tmax = fmaxf(tmax, __shfl_xor_sync(0xffffffffu, tmax, off));
            float m_new = fmaxf(m_run[i], tmax);
            float alpha = __expf(m_run[i] - m_new);
            float rsum = 0.f;
            #pragma unroll
            for (int j = 0; j < 4; j++) {
                sc[i][j] = __expf(sc[i][j] - m_new);
                rsum += sc[i][j];
            }
            #pragma unroll
            for (int off = 8; off; off >>= 1)
                rsum += __shfl_xor_sync(0xffffffffu, rsum, off);
            l_run[i] = l_run[i] * alpha + rsum;
            m_run[i] = m_new;
            #pragma unroll
            for (int j = 0; j < 4; j++) O[i][j] *= alpha;
            *(float4*)&Ps[(r0 + i) * LDA + c0] = *(float4*)&sc[i][0];
        }
        __syncthreads();

        // O += P V (4x4 per thread, d-cols c0..c0+3)
        #pragma unroll
        for (int cb = 0; cb < 64; cb += 4) {
            float4 pf[4], vf[4];
            #pragma unroll
            for (int i = 0; i < 4; i++) pf[i] = *(const float4*)&Ps[(r0 + i) * LDA + cb];
            #pragma unroll
            for (int u = 0; u < 4; u++) vf[u] = *(const float4*)&Vs[(cb + u) * LDA + c0];
            #pragma unroll
            for (int i = 0; i < 4; i++) {
                O[i][0] += pf[i].x * vf[0].x + pf[i].y * vf[1].x + pf[i].z * vf[2].x + pf[i].w * vf[3].x;
                O[i][1] += pf[i].x * vf[0].y + pf[i].y * vf[1].y + pf[i].z * vf[2].y + pf[i].w * vf[3].y;
                O[i][2] += pf[i].x * vf[0].z + pf[i].y * vf[1].z + pf[i].z * vf[2].z + pf[i].w * vf[3].z;
                O[i][3] += pf[i].x * vf[0].w + pf[i].y * vf[1].w + pf[i].z * vf[2].w + pf[i].w * vf[3].w;
            }
        }
        __syncthreads();
    }

    // epilogue: normalize and write ctx in [B, S, H*d] layout
    #pragma unroll
    for (int i = 0; i < 4; i++) {
        float inv = 1.f / l_run[i];
        int srow = qt * 64 + r0 + i;
        float4 o4 = make_float4(O[i][0] * inv, O[i][1] * inv, O[i][2] * inv, O[i][3] * inv);
        *(float4*)&g_ctx[((size_t)(b * NS + srow)) * ND + h * HD + c0] = o4;
    }
}

// ---------------------------------------------------------------------------
extern "C" void kernel_launch(void* const* d_in, const int* in_sizes, int n_in,
                              void* d_out, int out_size)
{
    const float* query = (const float*)d_in[0];
    const float* key   = (const float*)d_in[1];
    const float* value = (const float*)d_in[2];
    const float* wq = (const float*)d_in[3];
    const float* bq = (const float*)d_in[4];
    const float* wk = (const float*)d_in[5];
    const float* bk = (const float*)d_in[6];
    const float* wv = (const float*)d_in[7];
    const float* bv = (const float*)d_in[8];
    const float* wo = (const float*)d_in[9];
    const float* bo = (const float*)d_in[10];
    float* out = (float*)d_out;

    const int attn_smem = 4 * 64 * LDA * (int)sizeof(float); // 69632 B
    cudaFuncSetAttribute(attn_kernel,
                         cudaFuncAttributeMaxDynamicSharedMemorySize, attn_smem);

    dim3 ggrid(ND / 128, (NB * NS) / 128);
    sgemm_kernel<<<ggrid, 256>>>(query, wq, bq, nullptr, 1);
    sgemm_kernel<<<ggrid, 256>>>(key,   wk, bk, nullptr, 2);
    sgemm_kernel<<<ggrid, 256>>>(value, wv, bv, nullptr, 3);
    attn_kernel<<<dim3(NTILES, NH, NB), 256, attn_smem>>>();
    sgemm_kernel<<<ggrid, 256>>>(nullptr, wo, bo, out, 0);
}

// round 3
// speedup vs baseline: 3.8841x; 3.8841x over previous
#include <cuda_runtime.h>
#include <cuda_bf16.h>
#include <cstdint>
#include <math.h>

#define NB 4
#define NS 2048
#define ND 768
#define NH 12
#define HD 64
#define KVN (NB*NH*NS*HD)

// Scratch (device globals — no allocation allowed)
__device__ __align__(128) __nv_bfloat16 g_qh[KVN], g_ql[KVN];
__device__ __align__(128) __nv_bfloat16 g_kh[KVN], g_kl[KVN];
__device__ __align__(128) __nv_bfloat16 g_vh[KVN], g_vl[KVN];
__device__ __align__(128) float g_ctx[NB*NS*ND];

// ---------------------------------------------------------------------------
// helpers
// ---------------------------------------------------------------------------
__device__ __forceinline__ uint32_t s2u(const void* p) {
    return (uint32_t)__cvta_generic_to_shared(p);
}
__device__ __forceinline__ void ldm4(uint32_t* r, uint32_t addr) {
    asm volatile("ldmatrix.sync.aligned.m8n8.x4.shared.b16 {%0,%1,%2,%3}, [%4];"
                 : "=r"(r[0]), "=r"(r[1]), "=r"(r[2]), "=r"(r[3]) : "r"(addr));
}
__device__ __forceinline__ void ldm4t(uint32_t* r, uint32_t addr) {
    asm volatile("ldmatrix.sync.aligned.m8n8.x4.trans.shared.b16 {%0,%1,%2,%3}, [%4];"
                 : "=r"(r[0]), "=r"(r[1]), "=r"(r[2]), "=r"(r[3]) : "r"(addr));
}
__device__ __forceinline__ void mma16816(float* c, const uint32_t* a, const uint32_t* b) {
    asm volatile("mma.sync.aligned.m16n8k16.row.col.f32.bf16.bf16.f32 "
                 "{%0,%1,%2,%3}, {%4,%5,%6,%7}, {%8,%9}, {%0,%1,%2,%3};"
                 : "+f"(c[0]), "+f"(c[1]), "+f"(c[2]), "+f"(c[3])
                 : "r"(a[0]), "r"(a[1]), "r"(a[2]), "r"(a[3]), "r"(b[0]), "r"(b[1]));
}
__device__ __forceinline__ void cp16(uint32_t saddr, const void* g) {
    asm volatile("cp.async.cg.shared.global [%0], [%1], 16;" :: "r"(saddr), "l"(g) : "memory");
}
// split (x,y) into packed bf16x2 hi and lo (x in low half)
__device__ __forceinline__ void split2(float x, float y, uint32_t& hi, uint32_t& lo) {
    __nv_bfloat162 h = __floats2bfloat162_rn(x, y);
    __nv_bfloat162 l = __floats2bfloat162_rn(x - __low2float(h), y - __high2float(h));
    hi = *(uint32_t*)&h;
    lo = *(uint32_t*)&l;
}

// ---------------------------------------------------------------------------
// bf16x3 GEMM: 128x128 C tile, 256 threads, warp tile 32x64, K-block 32.
// mode 0: A = g_ctx -> fp32 out (+bias)
// mode 1/2/3: A = input -> split-head bf16 hi/lo to g_q*/g_k*/g_v*
//             (mode 1 also scales by 0.125 = 1/sqrt(64))
// ---------------------------------------------------------------------------
#define GA_LD 40
#define GB_LD 136
#define G_AH 0
#define G_AL 5120
#define G_BH 10240
#define G_BL 14592
#define G_BUF 18944   // bf16 elems per buffer; x2 buffers = 75776 bytes

__global__ void __launch_bounds__(256, 1) gemm_kernel(
    const float* __restrict__ Ain, const float* __restrict__ W,
    const float* __restrict__ bias, float* __restrict__ out_plain, const int mode)
{
    extern __shared__ char smraw[];
    __nv_bfloat16* sb = reinterpret_cast<__nv_bfloat16*>(smraw);

    const float* A = (mode == 0) ? g_ctx : Ain;
    const int t = threadIdx.x, lane = t & 31, warp = t >> 5;
    const int m0 = blockIdx.y * 128, n0 = blockIdx.x * 128;
    const int wm = (warp & 3) * 32, wn = (warp >> 2) * 64;
    const int g = lane >> 3;

    float acc[2][8][4];
    #pragma unroll
    for (int i = 0; i < 2; i++)
        #pragma unroll
        for (int j = 0; j < 8; j++)
            #pragma unroll
            for (int c = 0; c < 4; c++) acc[i][j][c] = 0.f;

    const int ar = t >> 3, akq = (t & 7) * 4;   // A tile: 128 rows x 32 k
    const int bkr = t >> 5, bn4 = (t & 31) * 4; // B tile: 32 k x 128 n

    float4 pa[4], pb[4];
    auto gload = [&](int k0) {
        #pragma unroll
        for (int i = 0; i < 4; i++) {
            pa[i] = *(const float4*)(A + (size_t)(m0 + ar + i * 32) * ND + k0 + akq);
            pb[i] = *(const float4*)(W + (size_t)(k0 + bkr + i * 8) * ND + n0 + bn4);
        }
    };
    auto sstore = [&](int buf) {
        __nv_bfloat16* base = sb + buf * G_BUF;
        #pragma unroll
        for (int i = 0; i < 4; i++) {
            {
                int arow = ar + i * 32;
                uint32_t h0, l0, h1, l1;
                split2(pa[i].x, pa[i].y, h0, l0);
                split2(pa[i].z, pa[i].w, h1, l1);
                uint32_t* Ah = (uint32_t*)(base + G_AH + arow * GA_LD + akq);
                uint32_t* Al = (uint32_t*)(base + G_AL + arow * GA_LD + akq);
                Ah[0] = h0; Ah[1] = h1;
                Al[0] = l0; Al[1] = l1;
            }
            {
                int brow = bkr + i * 8;
                uint32_t h0, l0, h1, l1;
                split2(pb[i].x, pb[i].y, h0, l0);
                split2(pb[i].z, pb[i].w, h1, l1);
                uint32_t* Bh = (uint32_t*)(base + G_BH + brow * GB_LD + bn4);
                uint32_t* Bl = (uint32_t*)(base + G_BL + brow * GB_LD + bn4);
                Bh[0] = h0; Bh[1] = h1;
                Bl[0] = l0; Bl[1] = l1;
            }
        }
    };

    gload(0);
    sstore(0);

    const int NK = ND / 32;  // 24
    for (int kb = 0; kb < NK; kb++) {
        __syncthreads();
        if (kb + 1 < NK) gload((kb + 1) * 32);
        const __nv_bfloat16* base = sb + (kb & 1) * G_BUF;
        #pragma unroll
        for (int ks = 0; ks < 32; ks += 16) {
            uint32_t ah[2][4], al[2][4];
            #pragma unroll
            for (int mt = 0; mt < 2; mt++) {
                uint32_t ad = s2u(base + G_AH + (wm + mt * 16 + (lane & 15)) * GA_LD
                                  + ks + (lane >> 4) * 8);
                ldm4(ah[mt], ad);
                ldm4(al[mt], ad + (G_AL - G_AH) * 2);
            }
            #pragma unroll
            for (int jg = 0; jg < 4; jg++) {
                uint32_t bd = s2u(base + G_BH + (ks + ((g & 1) << 3) + (lane & 7)) * GB_LD
                                  + wn + jg * 16 + ((g >> 1) << 3));
                uint32_t bh[4], bl[4];
                ldm4t(bh, bd);
                ldm4t(bl, bd + (G_BL - G_BH) * 2);
                #pragma unroll
                for (int mt = 0; mt < 2; mt++) {
                    #pragma unroll
                    for (int ss = 0; ss < 2; ss++) {
                        float* c = acc[mt][jg * 2 + ss];
                        mma16816(c, ah[mt], bh + ss * 2);
                        mma16816(c, ah[mt], bl + ss * 2);
                        mma16816(c, al[mt], bh + ss * 2);
                    }
                }
            }
        }
        __syncthreads();
        if (kb + 1 < NK) sstore((kb + 1) & 1);
    }

    // epilogue
    const float scq = (mode == 1) ? 0.125f : 1.0f;
    #pragma unroll
    for (int mt = 0; mt < 2; mt++) {
        #pragma unroll
        for (int j = 0; j < 8; j++) {
            int col = n0 + wn + j * 8 + (lane & 3) * 2;
            float b0 = __ldg(bias + col), b1 = __ldg(bias + col + 1);
            #pragma unroll
            for (int rr = 0; rr < 2; rr++) {
                int m = m0 + wm + mt * 16 + (lane >> 2) + rr * 8;
                float x = acc[mt][j][rr * 2] + b0;
                float y = acc[mt][j][rr * 2 + 1] + b1;
                if (mode == 0) {
                    *(float2*)&out_plain[(size_t)m * ND + col] = make_float2(x, y);
                } else {
                    x *= scq; y *= scq;
                    __nv_bfloat16* oh = (mode == 1) ? g_qh : (mode == 2) ? g_kh : g_vh;
                    __nv_bfloat16* ol = (mode == 1) ? g_ql : (mode == 2) ? g_kl : g_vl;
                    int bb = m >> 11, s = m & (NS - 1);
                    int hh = col >> 6, d = col & 63;
                    size_t idx = (((size_t)(bb * NH + hh)) * NS + s) * HD + d;
                    uint32_t hv, lv;
                    split2(x, y, hv, lv);
                    *(uint32_t*)(oh + idx) = hv;
                    *(uint32_t*)(ol + idx) = lv;
                }
            }
        }
    }
}

// ---------------------------------------------------------------------------
// Flash attention, bf16x3 mma. Block = (b, h, 128 q-rows), 8 warps.
// Warp: 16 q-rows x full 64-key tile -> warp-local softmax, P in registers.
// K/V via cp.async double buffer.
// ---------------------------------------------------------------------------
#define AT_LD 72
#define AT_QH 0
#define AT_QL 9216
#define AT_KV0 18432
#define AT_KBUF 18432   // per buffer: Kh 0, Kl 4608, Vh 9216, Vl 13824 (elems)

__global__ void __launch_bounds__(256, 1) attn_kernel()
{
    extern __shared__ char smraw2[];
    __nv_bfloat16* sb = reinterpret_cast<__nv_bfloat16*>(smraw2);

    const int t = threadIdx.x, lane = t & 31, warp = t >> 5;
    const int qt = blockIdx.x, hh = blockIdx.y, bb = blockIdx.z;
    const size_t hoff = ((size_t)(bb * NH + hh)) * NS * HD;
    const __nv_bfloat16* pqh = g_qh + hoff + (size_t)qt * 128 * HD;
    const __nv_bfloat16* pql = g_ql + hoff + (size_t)qt * 128 * HD;
    const __nv_bfloat16* pkh = g_kh + hoff;
    const __nv_bfloat16* pkl = g_kl + hoff;
    const __nv_bfloat16* pvh = g_vh + hoff;
    const __nv_bfloat16* pvl = g_vl + hoff;
    const int g = lane >> 3;

    // Q tile (128 x 64, hi+lo)
    #pragma unroll
    for (int i = 0; i < 8; i++) {
        int idx = t + i * 256;
        int arr = idx >> 10, id = idx & 1023;
        int r = id >> 3, c8 = (id & 7) * 8;
        const __nv_bfloat16* src = arr ? pql : pqh;
        __nv_bfloat16* dst = sb + (arr ? AT_QL : AT_QH);
        *(float4*)(dst + r * AT_LD + c8) = *(const float4*)(src + (size_t)r * HD + c8);
    }

    auto prefetch = [&](int jt, int buf) {
        __nv_bfloat16* kb = sb + AT_KV0 + buf * AT_KBUF;
        #pragma unroll
        for (int i = 0; i < 8; i++) {
            int idx = t + i * 256;
            int arr = idx >> 9, id = idx & 511;
            int r = id >> 3, c8 = (id & 7) * 8;
            const __nv_bfloat16* src = (arr == 0) ? pkh : (arr == 1) ? pkl
                                      : (arr == 2) ? pvh : pvl;
            cp16(s2u(kb + arr * 4608 + r * AT_LD + c8),
                 src + (size_t)(jt * 64 + r) * HD + c8);
        }
        asm volatile("cp.async.commit_group;" ::: "memory");
    };

    float sAcc[8][4], o[8][4];
    #pragma unroll
    for (int j = 0; j < 8; j++)
        #pragma unroll
        for (int c = 0; c < 4; c++) o[j][c] = 0.f;
    float mr0 = -1e30f, mr1 = -1e30f, lr0 = 0.f, lr1 = 0.f;

    const int mrow = warp * 16;

    prefetch(0, 0);

    const int NKT = NS / 64;  // 32
    for (int jt = 0; jt < NKT; jt++) {
        if (jt + 1 < NKT) {
            prefetch(jt + 1, (jt + 1) & 1);
            asm volatile("cp.async.wait_group 1;" ::: "memory");
        } else {
            asm volatile("cp.async.wait_group 0;" ::: "memory");
        }
        __syncthreads();

        const __nv_bfloat16* kvb = sb + AT_KV0 + (jt & 1) * AT_KBUF;
        const __nv_bfloat16* Kh = kvb;
        const __nv_bfloat16* Vh = kvb + 9216;

        // ---- S = Q K^T  (1/sqrt(d) folded into Q at projection)
        #pragma unroll
        for (int j = 0; j < 8; j++)
            #pragma unroll
            for (int c = 0; c < 4; c++) sAcc[j][c] = 0.f;

        #pragma unroll
        for (int ks = 0; ks < 64; ks += 16) {
            uint32_t qh4[4], ql4[4];
            uint32_t qad = s2u(sb + AT_QH + (mrow + (lane & 15)) * AT_LD
                               + ks + (lane >> 4) * 8);
            ldm4(qh4, qad);
            ldm4(ql4, qad + AT_QL * 2);
            #pragma unroll
            for (int jg = 0; jg < 4; jg++) {
                // K stored [key][d] == col-major B for row.col mma: non-trans ldmatrix
                uint32_t kad = s2u(Kh + (jg * 16 + ((g >> 1) << 3) + (lane & 7)) * AT_LD
                                   + ks + ((g & 1) << 3));
                uint32_t kh4[4], kl4[4];
                ldm4(kh4, kad);
                ldm4(kl4, kad + 4608 * 2);
                #pragma unroll
                for (int ss = 0; ss < 2; ss++) {
                    float* c = sAcc[jg * 2 + ss];
                    mma16816(c, qh4, kh4 + ss * 2);
                    mma16816(c, qh4, kl4 + ss * 2);
                    mma16816(c, ql4, kh4 + ss * 2);
                }
            }
        }

        // ---- online softmax (rows lane>>2 and +8; reduce over lane&3)
        float vx0 = -1e30f, vx1 = -1e30f;
        #pragma unroll
        for (int j = 0; j < 8; j++) {
            vx0 = fmaxf(vx0, fmaxf(sAcc[j][0], sAcc[j][1]));
            vx1 = fmaxf(vx1, fmaxf(sAcc[j][2], sAcc[j][3]));
        }
        vx0 = fmaxf(vx0, __shfl_xor_sync(0xffffffffu, vx0, 1));
        vx0 = fmaxf(vx0, __shfl_xor_sync(0xffffffffu, vx0, 2));
        vx1 = fmaxf(vx1, __shfl_xor_sync(0xffffffffu, vx1, 1));
        vx1 = fmaxf(vx1, __shfl_xor_sync(0xffffffffu, vx1, 2));
        float mn0 = fmaxf(mr0, vx0), mn1 = fmaxf(mr1, vx1);
        float al0 = __expf(mr0 - mn0), al1 = __expf(mr1 - mn1);
        float sm0 = 0.f, sm1 = 0.f;
        #pragma unroll
        for (int j = 0; j < 8; j++) {
            sAcc[j][0] = __expf(sAcc[j][0] - mn0); sm0 += sAcc[j][0];
            sAcc[j][1] = __expf(sAcc[j][1] - mn0); sm0 += sAcc[j][1];
            sAcc[j][2] = __expf(sAcc[j][2] - mn1); sm1 += sAcc[j][2];
            sAcc[j][3] = __expf(sAcc[j][3] - mn1); sm1 += sAcc[j][3];
        }
        sm0 += __shfl_xor_sync(0xffffffffu, sm0, 1);
        sm0 += __shfl_xor_sync(0xffffffffu, sm0, 2);
        sm1 += __shfl_xor_sync(0xffffffffu, sm1, 1);
        sm1 += __shfl_xor_sync(0xffffffffu, sm1, 2);
        lr0 = lr0 * al0 + sm0; lr1 = lr1 * al1 + sm1;
        mr0 = mn0; mr1 = mn1;
        #pragma unroll
        for (int j = 0; j < 8; j++) {
            o[j][0] *= al0; o[j][1] *= al0; o[j][2] *= al1; o[j][3] *= al1;
        }

        // ---- P fragments (hi/lo) straight from accumulators (A-frag layout)
        uint32_t ph[4][4], pl[4][4];
        #pragma unroll
        for (int kc = 0; kc < 4; kc++) {
            split2(sAcc[2*kc][0],   sAcc[2*kc][1],   ph[kc][0], pl[kc][0]);
            split2(sAcc[2*kc][2],   sAcc[2*kc][3],   ph[kc][1], pl[kc][1]);
            split2(sAcc[2*kc+1][0], sAcc[2*kc+1][1], ph[kc][2], pl[kc][2]);
            split2(sAcc[2*kc+1][2], sAcc[2*kc+1][3], ph[kc][3], pl[kc][3]);
        }

        // ---- O += P V   (V stored [key][d]: k-major B -> trans ldmatrix)
        #pragma unroll
        for (int kc = 0; kc < 4; kc++) {
            #pragma unroll
            for (int jg = 0; jg < 4; jg++) {
                uint32_t vad = s2u(Vh + (kc * 16 + ((g & 1) << 3) + (lane & 7)) * AT_LD
                                   + jg * 16 + ((g >> 1) << 3));
                uint32_t vh4[4], vl4[4];
                ldm4t(vh4, vad);
                ldm4t(vl4, vad + 4608 * 2);
                #pragma unroll
                for (int ss = 0; ss < 2; ss++) {
                    float* c = o[jg * 2 + ss];
                    mma16816(c, ph[kc], vh4 + ss * 2);
                    mma16816(c, ph[kc], vl4 + ss * 2);
                    mma16816(c, pl[kc], vh4 + ss * 2);
                }
            }
        }
        __syncthreads();   // all reads of this buffer done before next prefetch overwrites
    }

    // epilogue: normalize, write ctx [B, S, H*d] fp32
    float inv0 = 1.f / lr0, inv1 = 1.f / lr1;
    #pragma unroll
    for (int j = 0; j < 8; j++) {
        int col = hh * HD + j * 8 + (lane & 3) * 2;
        int r0 = qt * 128 + mrow + (lane >> 2);
        *(float2*)&g_ctx[((size_t)(bb * NS + r0)) * ND + col] =
            make_float2(o[j][0] * inv0, o[j][1] * inv0);
        *(float2*)&g_ctx[((size_t)(bb * NS + r0 + 8)) * ND + col] =
            make_float2(o[j][2] * inv1, o[j][3] * inv1);
    }
}

// ---------------------------------------------------------------------------
extern "C" void kernel_launch(void* const* d_in, const int* in_sizes, int n_in,
                              void* d_out, int out_size)
{
    const float* query = (const float*)d_in[0];
    const float* key   = (const float*)d_in[1];
    const float* value = (const float*)d_in[2];
    const float* wq = (const float*)d_in[3];
    const float* bq = (const float*)d_in[4];
    const float* wk = (const float*)d_in[5];
    const float* bk = (const float*)d_in[6];
    const float* wv = (const float*)d_in[7];
    const float* bv = (const float*)d_in[8];
    const float* wo = (const float*)d_in[9];
    const float* bo = (const float*)d_in[10];
    float* out = (float*)d_out;

    const int gemm_smem = 2 * G_BUF * 2;                  // 75776 B
    const int attn_smem = (AT_KV0 + 2 * AT_KBUF) * 2;     // 110592 B
    cudaFuncSetAttribute(gemm_kernel,
                         cudaFuncAttributeMaxDynamicSharedMemorySize, gemm_smem);
    cudaFuncSetAttribute(attn_kernel,
                         cudaFuncAttributeMaxDynamicSharedMemorySize, attn_smem);

    dim3 ggrid(ND / 128, (NB * NS) / 128);
    gemm_kernel<<<ggrid, 256, gemm_smem>>>(query, wq, bq, nullptr, 1);
    gemm_kernel<<<ggrid, 256, gemm_smem>>>(key,   wk, bk, nullptr, 2);
    gemm_kernel<<<ggrid, 256, gemm_smem>>>(value, wv, bv, nullptr, 3);
    attn_kernel<<<dim3(NS / 128, NH, NB), 256, attn_smem>>>();
    gemm_kernel<<<ggrid, 256, gemm_smem>>>(nullptr, wo, bo, out, 0);
}

// round 5
// speedup vs baseline: 4.3761x; 1.1267x over previous
#include <cuda_runtime.h>
#include <cuda_bf16.h>
#include <cstdint>
#include <math.h>

#define NB 4
#define NS 2048
#define ND 768
#define NH 12
#define HD 64
#define KVN (NB*NH*NS*HD)

// log2(e) * 1/sqrt(64) folded into Q projection -> softmax in exp2 domain
#define QSCALE 0.1803368801111f

// Scratch (device globals — no allocation allowed)
__device__ __align__(128) __nv_bfloat16 g_qh[KVN], g_ql[KVN];
__device__ __align__(128) __nv_bfloat16 g_kh[KVN], g_kl[KVN];
__device__ __align__(128) __nv_bfloat16 g_vh[KVN], g_vl[KVN];
__device__ __align__(128) float g_ctx[NB*NS*ND];

// ---------------------------------------------------------------------------
// helpers
// ---------------------------------------------------------------------------
__device__ __forceinline__ uint32_t s2u(const void* p) {
    return (uint32_t)__cvta_generic_to_shared(p);
}
__device__ __forceinline__ void ldm4(uint32_t* r, uint32_t addr) {
    asm volatile("ldmatrix.sync.aligned.m8n8.x4.shared.b16 {%0,%1,%2,%3}, [%4];"
                 : "=r"(r[0]), "=r"(r[1]), "=r"(r[2]), "=r"(r[3]) : "r"(addr));
}
__device__ __forceinline__ void ldm4t(uint32_t* r, uint32_t addr) {
    asm volatile("ldmatrix.sync.aligned.m8n8.x4.trans.shared.b16 {%0,%1,%2,%3}, [%4];"
                 : "=r"(r[0]), "=r"(r[1]), "=r"(r[2]), "=r"(r[3]) : "r"(addr));
}
__device__ __forceinline__ void mma16816(float* c, const uint32_t* a, const uint32_t* b) {
    asm volatile("mma.sync.aligned.m16n8k16.row.col.f32.bf16.bf16.f32 "
                 "{%0,%1,%2,%3}, {%4,%5,%6,%7}, {%8,%9}, {%0,%1,%2,%3};"
                 : "+f"(c[0]), "+f"(c[1]), "+f"(c[2]), "+f"(c[3])
                 : "r"(a[0]), "r"(a[1]), "r"(a[2]), "r"(a[3]), "r"(b[0]), "r"(b[1]));
}
__device__ __forceinline__ void cp16(uint32_t saddr, const void* g) {
    asm volatile("cp.async.cg.shared.global [%0], [%1], 16;" :: "r"(saddr), "l"(g) : "memory");
}
__device__ __forceinline__ float ex2(float x) {
    float r; asm("ex2.approx.ftz.f32 %0, %1;" : "=f"(r) : "f"(x)); return r;
}
// split (x,y) into packed bf16x2 hi and lo (x in low half)
__device__ __forceinline__ void split2(float x, float y, uint32_t& hi, uint32_t& lo) {
    __nv_bfloat162 h = __floats2bfloat162_rn(x, y);
    __nv_bfloat162 l = __floats2bfloat162_rn(x - __low2float(h), y - __high2float(h));
    hi = *(uint32_t*)&h;
    lo = *(uint32_t*)&l;
}

// ---------------------------------------------------------------------------
// bf16x3 GEMM mainloop: 128x128 C tile, 256 threads, warp tile 32x64, kblk 32
// ---------------------------------------------------------------------------
#define GA_LD 40
#define GB_LD 136
#define G_AH 0
#define G_AL 5120
#define G_BH 10240
#define G_BL 14592
#define G_BUF 18944   // bf16 elems per buffer; x2 buffers = 75776 bytes

__device__ __forceinline__ void gemm_main(
    const float* __restrict__ A, const float* __restrict__ W,
    __nv_bfloat16* sb, int m0, int n0, float acc[2][8][4])
{
    const int t = threadIdx.x, lane = t & 31, warp = t >> 5;
    const int wm = (warp & 3) * 32, wn = (warp >> 2) * 64;
    const int g = lane >> 3;

    const int ar = t >> 3, akq = (t & 7) * 4;   // A tile: 128 rows x 32 k
    const int bkr = t >> 5, bn4 = (t & 31) * 4; // B tile: 32 k x 128 n

    float4 pa[4], pb[4];
    auto gload = [&](int k0) {
        #pragma unroll
        for (int i = 0; i < 4; i++) {
            pa[i] = *(const float4*)(A + (size_t)(m0 + ar + i * 32) * ND + k0 + akq);
            pb[i] = *(const float4*)(W + (size_t)(k0 + bkr + i * 8) * ND + n0 + bn4);
        }
    };
    auto sstore = [&](int buf) {
        __nv_bfloat16* base = sb + buf * G_BUF;
        #pragma unroll
        for (int i = 0; i < 4; i++) {
            {
                int arow = ar + i * 32;
                uint32_t h0, l0, h1, l1;
                split2(pa[i].x, pa[i].y, h0, l0);
                split2(pa[i].z, pa[i].w, h1, l1);
                uint32_t* Ah = (uint32_t*)(base + G_AH + arow * GA_LD + akq);
                uint32_t* Al = (uint32_t*)(base + G_AL + arow * GA_LD + akq);
                Ah[0] = h0; Ah[1] = h1;
                Al[0] = l0; Al[1] = l1;
            }
            {
                int brow = bkr + i * 8;
                uint32_t h0, l0, h1, l1;
                split2(pb[i].x, pb[i].y, h0, l0);
                split2(pb[i].z, pb[i].w, h1, l1);
                uint32_t* Bh = (uint32_t*)(base + G_BH + brow * GB_LD + bn4);
                uint32_t* Bl = (uint32_t*)(base + G_BL + brow * GB_LD + bn4);
                Bh[0] = h0; Bh[1] = h1;
                Bl[0] = l0; Bl[1] = l1;
            }
        }
    };

    gload(0);
    sstore(0);

    const int NK = ND / 32;  // 24
    for (int kb = 0; kb < NK; kb++) {
        __syncthreads();
        if (kb + 1 < NK) gload((kb + 1) * 32);
        const __nv_bfloat16* base = sb + (kb & 1) * G_BUF;
        #pragma unroll
        for (int ks = 0; ks < 32; ks += 16) {
            uint32_t ah[2][4], al[2][4];
            #pragma unroll
            for (int mt = 0; mt < 2; mt++) {
                uint32_t ad = s2u(base + G_AH + (wm + mt * 16 + (lane & 15)) * GA_LD
                                  + ks + (lane >> 4) * 8);
                ldm4(ah[mt], ad);
                ldm4(al[mt], ad + (G_AL - G_AH) * 2);
            }
            #pragma unroll
            for (int jg = 0; jg < 4; jg++) {
                uint32_t bd = s2u(base + G_BH + (ks + ((g & 1) << 3) + (lane & 7)) * GB_LD
                                  + wn + jg * 16 + ((g >> 1) << 3));
                uint32_t bh[4], bl[4];
                ldm4t(bh, bd);
                ldm4t(bl, bd + (G_BL - G_BH) * 2);
                #pragma unroll
                for (int mt = 0; mt < 2; mt++) {
                    #pragma unroll
                    for (int ss = 0; ss < 2; ss++) {
                        float* c = acc[mt][jg * 2 + ss];
                        mma16816(c, ah[mt], bh + ss * 2);
                        mma16816(c, ah[mt], bl + ss * 2);
                        mma16816(c, al[mt], bh + ss * 2);
                    }
                }
            }
        }
        __syncthreads();
        if (kb + 1 < NK) sstore((kb + 1) & 1);
    }
}

// ---------------------------------------------------------------------------
// merged QKV projection (grid z = 0/1/2 -> q/k/v), split-head bf16 hi/lo out
// ---------------------------------------------------------------------------
__global__ void __launch_bounds__(256, 1) qkv_gemm(
    const float* __restrict__ q_in, const float* __restrict__ k_in,
    const float* __restrict__ v_in,
    const float* __restrict__ wq, const float* __restrict__ wk,
    const float* __restrict__ wv,
    const float* __restrict__ bq, const float* __restrict__ bk,
    const float* __restrict__ bv)
{
    extern __shared__ char smraw[];
    __nv_bfloat16* sb = reinterpret_cast<__nv_bfloat16*>(smraw);

    const int z = blockIdx.z;
    const float* A    = (z == 0) ? q_in : (z == 1) ? k_in : v_in;
    const float* W    = (z == 0) ? wq   : (z == 1) ? wk   : wv;
    const float* bias = (z == 0) ? bq   : (z == 1) ? bk   : bv;
    __nv_bfloat16* oh = (z == 0) ? g_qh : (z == 1) ? g_kh : g_vh;
    __nv_bfloat16* ol = (z == 0) ? g_ql : (z == 1) ? g_kl : g_vl;
    const float sc = (z == 0) ? QSCALE : 1.0f;

    const int m0 = blockIdx.y * 128, n0 = blockIdx.x * 128;

    float acc[2][8][4];
    #pragma unroll
    for (int i = 0; i < 2; i++)
        #pragma unroll
        for (int j = 0; j < 8; j++)
            #pragma unroll
            for (int c = 0; c < 4; c++) acc[i][j][c] = 0.f;

    gemm_main(A, W, sb, m0, n0, acc);

    const int lane = threadIdx.x & 31, warp = threadIdx.x >> 5;
    const int wm = (warp & 3) * 32, wn = (warp >> 2) * 64;
    #pragma unroll
    for (int mt = 0; mt < 2; mt++) {
        #pragma unroll
        for (int j = 0; j < 8; j++) {
            int col = n0 + wn + j * 8 + (lane & 3) * 2;
            float b0 = __ldg(bias + col), b1 = __ldg(bias + col + 1);
            #pragma unroll
            for (int rr = 0; rr < 2; rr++) {
                int m = m0 + wm + mt * 16 + (lane >> 2) + rr * 8;
                float x = (acc[mt][j][rr * 2] + b0) * sc;
                float y = (acc[mt][j][rr * 2 + 1] + b1) * sc;
                int bb = m >> 11, s = m & (NS - 1);
                int hh = col >> 6, d = col & 63;
                size_t idx = (((size_t)(bb * NH + hh)) * NS + s) * HD + d;
                uint32_t hv, lv;
                split2(x, y, hv, lv);
                *(uint32_t*)(oh + idx) = hv;
                *(uint32_t*)(ol + idx) = lv;
            }
        }
    }
}

// ---------------------------------------------------------------------------
// output projection: g_ctx @ wo + bo -> fp32 out
// ---------------------------------------------------------------------------
__global__ void __launch_bounds__(256, 1) out_gemm(
    const float* __restrict__ W, const float* __restrict__ bias,
    float* __restrict__ out)
{
    extern __shared__ char smraw[];
    __nv_bfloat16* sb = reinterpret_cast<__nv_bfloat16*>(smraw);
    const int m0 = blockIdx.y * 128, n0 = blockIdx.x * 128;

    float acc[2][8][4];
    #pragma unroll
    for (int i = 0; i < 2; i++)
        #pragma unroll
        for (int j = 0; j < 8; j++)
            #pragma unroll
            for (int c = 0; c < 4; c++) acc[i][j][c] = 0.f;

    gemm_main(g_ctx, W, sb, m0, n0, acc);

    const int lane = threadIdx.x & 31, warp = threadIdx.x >> 5;
    const int wm = (warp & 3) * 32, wn = (warp >> 2) * 64;
    #pragma unroll
    for (int mt = 0; mt < 2; mt++) {
        #pragma unroll
        for (int j = 0; j < 8; j++) {
            int col = n0 + wn + j * 8 + (lane & 3) * 2;
            float b0 = __ldg(bias + col), b1 = __ldg(bias + col + 1);
            #pragma unroll
            for (int rr = 0; rr < 2; rr++) {
                int m = m0 + wm + mt * 16 + (lane >> 2) + rr * 8;
                *(float2*)&out[(size_t)m * ND + col] =
                    make_float2(acc[mt][j][rr * 2] + b0, acc[mt][j][rr * 2 + 1] + b1);
            }
        }
    }
}

// ---------------------------------------------------------------------------
// Flash attention, bf16x3 mma. Block = (b, h, 128 q-rows), 8 warps,
// 2 CTAs/SM (regs capped at 128) so independent CTAs overlap softmax vs MMA.
// ---------------------------------------------------------------------------
#define AT_LD 72
#define AT_QH 0
#define AT_QL 9216
#define AT_KV0 18432
#define AT_KBUF 18432   // per buffer: Kh 0, Kl 4608, Vh 9216, Vl 13824 (elems)

__global__ void __launch_bounds__(256, 2) attn_kernel()
{
    extern __shared__ char smraw2[];
    __nv_bfloat16* sb = reinterpret_cast<__nv_bfloat16*>(smraw2);

    const int t = threadIdx.x, lane = t & 31, warp = t >> 5;
    const int qt = blockIdx.x, hh = blockIdx.y, bb = blockIdx.z;
    const size_t hoff = ((size_t)(bb * NH + hh)) * NS * HD;
    const __nv_bfloat16* pqh = g_qh + hoff + (size_t)qt * 128 * HD;
    const __nv_bfloat16* pql = g_ql + hoff + (size_t)qt * 128 * HD;
    const __nv_bfloat16* pkh = g_kh + hoff;
    const __nv_bfloat16* pkl = g_kl + hoff;
    const __nv_bfloat16* pvh = g_vh + hoff;
    const __nv_bfloat16* pvl = g_vl + hoff;
    const int g = lane >> 3;

    // Q tile (128 x 64, hi+lo)
    #pragma unroll
    for (int i = 0; i < 8; i++) {
        int idx = t + i * 256;
        int arr = idx >> 10, id = idx & 1023;
        int r = id >> 3, c8 = (id & 7) * 8;
        const __nv_bfloat16* src = arr ? pql : pqh;
        __nv_bfloat16* dst = sb + (arr ? AT_QL : AT_QH);
        *(float4*)(dst + r * AT_LD + c8) = *(const float4*)(src + (size_t)r * HD + c8);
    }

    auto prefetch = [&](int jt, int buf) {
        __nv_bfloat16* kb = sb + AT_KV0 + buf * AT_KBUF;
        #pragma unroll
        for (int i = 0; i < 8; i++) {
            int idx = t + i * 256;
            int arr = idx >> 9, id = idx & 511;
            int r = id >> 3, c8 = (id & 7) * 8;
            const __nv_bfloat16* src = (arr == 0) ? pkh : (arr == 1) ? pkl
                                      : (arr == 2) ? pvh : pvl;
            cp16(s2u(kb + arr * 4608 + r * AT_LD + c8),
                 src + (size_t)(jt * 64 + r) * HD + c8);
        }
        asm volatile("cp.async.commit_group;" ::: "memory");
    };

    float sAcc[8][4], o[8][4];
    #pragma unroll
    for (int j = 0; j < 8; j++)
        #pragma unroll
        for (int c = 0; c < 4; c++) o[j][c] = 0.f;
    float mr0 = -1e30f, mr1 = -1e30f, lr0 = 0.f, lr1 = 0.f;

    const int mrow = warp * 16;

    prefetch(0, 0);

    const int NKT = NS / 64;  // 32
    for (int jt = 0; jt < NKT; jt++) {
        if (jt + 1 < NKT) {
            prefetch(jt + 1, (jt + 1) & 1);
            asm volatile("cp.async.wait_group 1;" ::: "memory");
        } else {
            asm volatile("cp.async.wait_group 0;" ::: "memory");
        }
        __syncthreads();

        const __nv_bfloat16* kvb = sb + AT_KV0 + (jt & 1) * AT_KBUF;
        const __nv_bfloat16* Kh = kvb;
        const __nv_bfloat16* Vh = kvb + 9216;

        // ---- S = Q K^T  (QSCALE folded into Q at projection; exp2 domain)
        #pragma unroll
        for (int j = 0; j < 8; j++)
            #pragma unroll
            for (int c = 0; c < 4; c++) sAcc[j][c] = 0.f;

        #pragma unroll
        for (int ks = 0; ks < 64; ks += 16) {
            uint32_t qh4[4], ql4[4];
            uint32_t qad = s2u(sb + AT_QH + (mrow + (lane & 15)) * AT_LD
                               + ks + (lane >> 4) * 8);
            ldm4(qh4, qad);
            ldm4(ql4, qad + AT_QL * 2);
            #pragma unroll
            for (int jg = 0; jg < 4; jg++) {
                uint32_t kad = s2u(Kh + (jg * 16 + ((g >> 1) << 3) + (lane & 7)) * AT_LD
                                   + ks + ((g & 1) << 3));
                uint32_t kh4[4], kl4[4];
                ldm4(kh4, kad);
                ldm4(kl4, kad + 4608 * 2);
                #pragma unroll
                for (int ss = 0; ss < 2; ss++) {
                    float* c = sAcc[jg * 2 + ss];
                    mma16816(c, qh4, kh4 + ss * 2);
                    mma16816(c, qh4, kl4 + ss * 2);
                    mma16816(c, ql4, kh4 + ss * 2);
                }
            }
        }

        // ---- online softmax in exp2 domain (rows lane>>2, +8; reduce lane&3)
        float vx0 = -1e30f, vx1 = -1e30f;
        #pragma unroll
        for (int j = 0; j < 8; j++) {
            vx0 = fmaxf(vx0, fmaxf(sAcc[j][0], sAcc[j][1]));
            vx1 = fmaxf(vx1, fmaxf(sAcc[j][2], sAcc[j][3]));
        }
        vx0 = fmaxf(vx0, __shfl_xor_sync(0xffffffffu, vx0, 1));
        vx0 = fmaxf(vx0, __shfl_xor_sync(0xffffffffu, vx0, 2));
        vx1 = fmaxf(vx1, __shfl_xor_sync(0xffffffffu, vx1, 1));
        vx1 = fmaxf(vx1, __shfl_xor_sync(0xffffffffu, vx1, 2));
        float mn0 = fmaxf(mr0, vx0), mn1 = fmaxf(mr1, vx1);
        float al0 = ex2(mr0 - mn0), al1 = ex2(mr1 - mn1);
        float sm0 = 0.f, sm1 = 0.f;
        #pragma unroll
        for (int j = 0; j < 8; j++) {
            sAcc[j][0] = ex2(sAcc[j][0] - mn0); sm0 += sAcc[j][0];
            sAcc[j][1] = ex2(sAcc[j][1] - mn0); sm0 += sAcc[j][1];
            sAcc[j][2] = ex2(sAcc[j][2] - mn1); sm1 += sAcc[j][2];
            sAcc[j][3] = ex2(sAcc[j][3] - mn1); sm1 += sAcc[j][3];
        }
        sm0 += __shfl_xor_sync(0xffffffffu, sm0, 1);
        sm0 += __shfl_xor_sync(0xffffffffu, sm0, 2);
        sm1 += __shfl_xor_sync(0xffffffffu, sm1, 1);
        sm1 += __shfl_xor_sync(0xffffffffu, sm1, 2);
        lr0 = lr0 * al0 + sm0; lr1 = lr1 * al1 + sm1;
        mr0 = mn0; mr1 = mn1;
        #pragma unroll
        for (int j = 0; j < 8; j++) {
            o[j][0] *= al0; o[j][1] *= al0; o[j][2] *= al1; o[j][3] *= al1;
        }

        // ---- O += P V   (P split inside kc loop -> only 8 live P regs)
        #pragma unroll
        for (int kc = 0; kc < 4; kc++) {
            uint32_t ph[4], pl[4];
            split2(sAcc[2*kc][0],   sAcc[2*kc][1],   ph[0], pl[0]);
            split2(sAcc[2*kc][2],   sAcc[2*kc][3],   ph[1], pl[1]);
            split2(sAcc[2*kc+1][0], sAcc[2*kc+1][1], ph[2], pl[2]);
            split2(sAcc[2*kc+1][2], sAcc[2*kc+1][3], ph[3], pl[3]);
            #pragma unroll
            for (int jg = 0; jg < 4; jg++) {
                uint32_t vad = s2u(Vh + (kc * 16 + ((g & 1) << 3) + (lane & 7)) * AT_LD
                                   + jg * 16 + ((g >> 1) << 3));
                uint32_t vh4[4], vl4[4];
                ldm4t(vh4, vad);
                ldm4t(vl4, vad + 4608 * 2);
                #pragma unroll
                for (int ss = 0; ss < 2; ss++) {
                    float* c = o[jg * 2 + ss];
                    mma16816(c, ph, vh4 + ss * 2);
                    mma16816(c, ph, vl4 + ss * 2);
                    mma16816(c, pl, vh4 + ss * 2);
                }
            }
        }
        __syncthreads();   // all reads of this buffer done before next prefetch
    }

    // epilogue: normalize, write ctx [B, S, H*d] fp32
    float inv0 = 1.f / lr0, inv1 = 1.f / lr1;
    #pragma unroll
    for (int j = 0; j < 8; j++) {
        int col = hh * HD + j * 8 + (lane & 3) * 2;
        int r0 = qt * 128 + mrow + (lane >> 2);
        *(float2*)&g_ctx[((size_t)(bb * NS + r0)) * ND + col] =
            make_float2(o[j][0] * inv0, o[j][1] * inv0);
        *(float2*)&g_ctx[((size_t)(bb * NS + r0 + 8)) * ND + col] =
            make_float2(o[j][2] * inv1, o[j][3] * inv1);
    }
}

// ---------------------------------------------------------------------------
extern "C" void kernel_launch(void* const* d_in, const int* in_sizes, int n_in,
                              void* d_out, int out_size)
{
    const float* query = (const float*)d_in[0];
    const float* key   = (const float*)d_in[1];
    const float* value = (const float*)d_in[2];
    const float* wq = (const float*)d_in[3];
    const float* bq = (const float*)d_in[4];
    const float* wk = (const float*)d_in[5];
    const float* bk = (const float*)d_in[6];
    const float* wv = (const float*)d_in[7];
    const float* bv = (const float*)d_in[8];
    const float* wo = (const float*)d_in[9];
    const float* bo = (const float*)d_in[10];
    float* out = (float*)d_out;

    const int gemm_smem = 2 * G_BUF * 2;                  // 75776 B
    const int attn_smem = (AT_KV0 + 2 * AT_KBUF) * 2;     // 110592 B
    cudaFuncSetAttribute(qkv_gemm,
                         cudaFuncAttributeMaxDynamicSharedMemorySize, gemm_smem);
    cudaFuncSetAttribute(out_gemm,
                         cudaFuncAttributeMaxDynamicSharedMemorySize, gemm_smem);
    cudaFuncSetAttribute(attn_kernel,
                         cudaFuncAttributeMaxDynamicSharedMemorySize, attn_smem);

    qkv_gemm<<<dim3(ND / 128, (NB * NS) / 128, 3), 256, gemm_smem>>>(
        query, key, value, wq, wk, wv, bq, bk, bv);
    attn_kernel<<<dim3(NS / 128, NH, NB), 256, attn_smem>>>();
    out_gemm<<<dim3(ND / 128, (NB * NS) / 128), 256, gemm_smem>>>(wo, bo, out);
}